// round 15
// baseline (speedup 1.0000x reference)
#include <cuda_runtime.h>
#include <cuda_bf16.h>

#define BB 512
#define SS 512
#define CC 96
#define NB 8                    // batches per CTA (one MMA N-tile)
#define FWD_T 192               // forward threads (6 warps)
#define ALL_T 256               // + 2 numerator warps
#define SUP 144                 // u row stride (bf16): 288B -> 2-phase LDS.64
#define SEP 108                 // em row pad (f32), 16B multiple

__device__ float g_num[BB];
__device__ float g_den[BB];

__device__ __forceinline__ float fast_rcp(float x) {
    float r;
    asm("rcp.approx.f32 %0, %1;" : "=f"(r) : "f"(x));
    return r;
}
__device__ __forceinline__ unsigned pack_bf16(float x, float y) {
    __nv_bfloat162 h = __floats2bfloat162_rn(x, y);
    return *reinterpret_cast<unsigned*>(&h);
}
__device__ __forceinline__ void mma_bf16(
    float& d0, float& d1, float& d2, float& d3,
    unsigned a0, unsigned a1, unsigned a2, unsigned a3,
    unsigned b0, unsigned b1)
{
    asm volatile(
        "mma.sync.aligned.m16n8k16.row.col.f32.bf16.bf16.f32 "
        "{%0,%1,%2,%3},{%4,%5,%6,%7},{%8,%9},{%0,%1,%2,%3};"
        : "+f"(d0), "+f"(d1), "+f"(d2), "+f"(d3)
        : "r"(a0), "r"(a1), "r"(a2), "r"(a3), "r"(b0), "r"(b1));
}
__device__ __forceinline__ void cp_async16(void* dst, const void* src) {
    unsigned d = (unsigned)__cvta_generic_to_shared(dst);
    asm volatile("cp.async.cg.shared.global [%0], [%1], 16;" :: "r"(d), "l"(src));
}
__device__ __forceinline__ void cp_async4(void* dst, const void* src) {
    unsigned d = (unsigned)__cvta_generic_to_shared(dst);
    asm volatile("cp.async.ca.shared.global [%0], [%1], 4;" :: "r"(d), "l"(src));
}
#define CP_COMMIT() asm volatile("cp.async.commit_group;" ::: "memory")
#define CP_WAIT2()  asm volatile("cp.async.wait_group 2;" ::: "memory")
#define FBAR()      asm volatile("bar.sync 1, %0;" :: "r"(FWD_T) : "memory")

// fragment-friendly permutation of the state index
__device__ __forceinline__ int perm96(int s) {
    int base = s & ~15, r = s & 15, hi = r >> 3, low = r & 7;
    return base + 4 * (low >> 1) + 2 * hi + (low & 1);
}

// =====================================================================
// Fused forward + numerator. 64 CTAs x 256 threads.
// Threads 0..191 (6 warps): tensor-core forward recurrence for 8
// batches (named barrier 1). Threads 192..255 (2 warps): numerator for
// the same 8 batches, free-running.
// =====================================================================
__global__ __launch_bounds__(ALL_T, 1) void crf_fused_kernel(
    const float* __restrict__ em,
    const int* __restrict__ tags,
    const int* __restrict__ masks,
    const float* __restrict__ start,
    const float* __restrict__ endt,
    const float* __restrict__ trans)
{
    __shared__ __align__(16) __nv_bfloat16 s_u[2][NB][SUP];
    __shared__ __align__(16) float s_em[4][NB * SEP];
    __shared__ float s_r[2][NB];
    __shared__ int   s_mk[4][NB];
    __shared__ float s_ee[CC];
    __shared__ float s_S[NB];

    const int tid = threadIdx.x;
    const int b0g = blockIdx.x * NB;

    // ================= numerator warps =================
    if (tid >= FWD_T) {
        const int w2 = (tid - FWD_T) >> 5;   // 0..1
        const int lane = tid & 31;
#pragma unroll
        for (int k = 0; k < 4; k++) {
            const int b = b0g + w2 * 4 + k;
            const int* tg = tags + (size_t)b * SS;
            const int* mk = masks + (size_t)b * SS;
            const float* e = em + (size_t)b * SS * CC;
            float s = 0.f;
            int cnt = 0;
            for (int t = lane; t < SS; t += 32) {
                int tagt = tg[t];
                int m = mk[t];
                cnt += m ? 1 : 0;
                if (t == 0) {
                    s += start[tagt] + e[tagt];
                } else if (m) {
                    int tp = tg[t - 1];
                    s += trans[tp * CC + tagt] + e[(size_t)t * CC + tagt];
                }
            }
#pragma unroll
            for (int o = 16; o; o >>= 1) {
                s += __shfl_xor_sync(0xFFFFFFFFu, s, o);
                cnt += __shfl_xor_sync(0xFFFFFFFFu, cnt, o);
            }
            if (lane == 0) g_num[b] = s + endt[tg[cnt - 1]];
        }
        return;
    }

    // ================= forward warps =================
    const int mt   = tid >> 5;          // M-tile (16 states)
    const int lane = tid & 31;
    const int lr   = lane >> 2;
    const int lc   = lane & 3;

    const int s0 = 16 * mt + lr, s1 = s0 + 8;
    const int n0 = 2 * lc, n1 = n0 + 1;
    const int ps0 = 16 * mt + 4 * (lr >> 1) + (lr & 1);  // perm(s0)
    const int ps1 = ps0 + 2;                             // perm(s1)

    const int cp_n = tid / 24, cp_s = (tid % 24) * 4;
    const float* em_src_base = em + (size_t)(b0g + cp_n) * SS * CC + cp_s;

    // A fragments: A[m][k] = exp(trans[k][m])
    unsigned A[6][4];
#pragma unroll
    for (int kt = 0; kt < 6; kt++) {
        int k0 = 16 * kt + 2 * lc;
        A[kt][0] = pack_bf16(__expf(trans[(k0 + 0) * CC + s0]), __expf(trans[(k0 + 1) * CC + s0]));
        A[kt][1] = pack_bf16(__expf(trans[(k0 + 0) * CC + s1]), __expf(trans[(k0 + 1) * CC + s1]));
        A[kt][2] = pack_bf16(__expf(trans[(k0 + 8) * CC + s0]), __expf(trans[(k0 + 9) * CC + s0]));
        A[kt][3] = pack_bf16(__expf(trans[(k0 + 8) * CC + s1]), __expf(trans[(k0 + 9) * CC + s1]));
    }

    // t = 0 state
    float u00 = __expf(start[s0] + em[(size_t)(b0g + n0) * SS * CC + s0]);
    float u01 = __expf(start[s0] + em[(size_t)(b0g + n1) * SS * CC + s0]);
    float u10 = __expf(start[s1] + em[(size_t)(b0g + n0) * SS * CC + s1]);
    float u11 = __expf(start[s1] + em[(size_t)(b0g + n1) * SS * CC + s1]);
    s_u[0][n0][ps0] = __float2bfloat16(u00);
    s_u[0][n1][ps0] = __float2bfloat16(u01);
    s_u[0][n0][ps1] = __float2bfloat16(u10);
    s_u[0][n1][ps1] = __float2bfloat16(u11);
    float S0 = 0.f, S1 = 0.f;
    if (mt == 0 && lr == 0) {
        s_r[0][n0] = fast_rcp(u00);
        s_r[0][n1] = fast_rcp(u01);
    }
    if (tid < CC) s_ee[perm96(tid)] = __expf(endt[tid]);

    // prologue: stage em/mask for t = 1,2,3
#pragma unroll
    for (int tt = 1; tt <= 3; tt++) {
        cp_async16(&s_em[tt & 3][cp_n * SEP + cp_s], em_src_base + (size_t)tt * CC);
        if (tid < NB) cp_async4(&s_mk[tt & 3][tid], masks + (size_t)(b0g + tid) * SS + tt);
        CP_COMMIT();
    }
    CP_WAIT2();          // em/mask for t=1 complete

    // E for t = 1 (from completed buffer 1)
    float E00 = __expf(s_em[1][n0 * SEP + s0]);
    float E01 = __expf(s_em[1][n1 * SEP + s0]);
    float E10 = __expf(s_em[1][n0 * SEP + s1]);
    float E11 = __expf(s_em[1][n1 * SEP + s1]);
    FBAR();

    int p = 0;
    for (int t = 1; t < SS; t++) {
        // prefetch t+3
        int tp = t + 3;
        if (tp < SS) {
            cp_async16(&s_em[tp & 3][cp_n * SEP + cp_s], em_src_base + (size_t)tp * CC);
            if (tid < NB) cp_async4(&s_mk[tp & 3][tid], masks + (size_t)(b0g + tid) * SS + tp);
        }
        CP_COMMIT();

        const int eb = t & 3;
        // iteration-start scalars (off critical path)
        float r0 = s_r[p][n0], r1 = s_r[p][n1];
        int m0 = s_mk[eb][n0], m1 = s_mk[eb][n1];
        float er00 = E00 * r0, er01 = E01 * r1;
        float er10 = E10 * r0, er11 = E11 * r1;

        // B fragments: 6 LDS.64 from permuted u
        uint2 bb[6];
#pragma unroll
        for (int kt = 0; kt < 6; kt++)
            bb[kt] = *(const uint2*)&s_u[p][lr][16 * kt + 4 * lc];

        // 3 independent 2-deep MMA chains
        float a0 = 0.f, a1 = 0.f, a2 = 0.f, a3 = 0.f;
        float b0 = 0.f, b1 = 0.f, b2 = 0.f, b3 = 0.f;
        float c0 = 0.f, c1 = 0.f, c2 = 0.f, c3 = 0.f;
        mma_bf16(a0, a1, a2, a3, A[0][0], A[0][1], A[0][2], A[0][3], bb[0].x, bb[0].y);
        mma_bf16(b0, b1, b2, b3, A[1][0], A[1][1], A[1][2], A[1][3], bb[1].x, bb[1].y);
        mma_bf16(c0, c1, c2, c3, A[2][0], A[2][1], A[2][2], A[2][3], bb[2].x, bb[2].y);
        mma_bf16(a0, a1, a2, a3, A[3][0], A[3][1], A[3][2], A[3][3], bb[3].x, bb[3].y);
        mma_bf16(b0, b1, b2, b3, A[4][0], A[4][1], A[4][2], A[4][3], bb[4].x, bb[4].y);
        mma_bf16(c0, c1, c2, c3, A[5][0], A[5][1], A[5][2], A[5][3], bb[5].x, bb[5].y);

        // E for t+1 under the MMA shadow (buffer (t+1)&3 complete since
        // end of iter t-1; garbage-but-unused at t = SS-1)
        const int en = (t + 1) & 3;
        float nE00 = __expf(s_em[en][n0 * SEP + s0]);
        float nE01 = __expf(s_em[en][n1 * SEP + s0]);
        float nE10 = __expf(s_em[en][n0 * SEP + s1]);
        float nE11 = __expf(s_em[en][n1 * SEP + s1]);

        float d0 = (a0 + b0) + c0;
        float d1 = (a1 + b1) + c1;
        float d2 = (a2 + b2) + c2;
        float d3 = (a3 + b3) + c3;

        // epilogue: mul + sel + pack + store
        float v00 = d0 * er00, v01 = d1 * er01;
        float v10 = d2 * er10, v11 = d3 * er11;
        u00 = m0 ? v00 : u00;  u01 = m1 ? v01 : u01;
        u10 = m0 ? v10 : u10;  u11 = m1 ? v11 : u11;
        s_u[p ^ 1][n0][ps0] = __float2bfloat16(u00);
        s_u[p ^ 1][n1][ps0] = __float2bfloat16(u01);
        s_u[p ^ 1][n0][ps1] = __float2bfloat16(u10);
        s_u[p ^ 1][n1][ps1] = __float2bfloat16(u11);
        if (mt == 0 && lr == 0) {
            s_r[p ^ 1][n0] = m0 ? fast_rcp(u00) : r0;
            s_r[p ^ 1][n1] = m1 ? fast_rcp(u01) : r1;
            S0 = m0 ? S0 - __logf(r0) : S0;
            S1 = m1 ? S1 - __logf(r1) : S1;
        }

        E00 = nE00; E01 = nE01; E10 = nE10; E11 = nE11;

        CP_WAIT2();
        FBAR();
        p ^= 1;
    }

    if (mt == 0 && lr == 0) { s_S[n0] = S0; s_S[n1] = S1; }
    FBAR();
    if (tid < NB) {
        float s = 0.f;
        for (int j = 0; j < CC; j++)
            s += __bfloat162float(s_u[p][tid][j]) * s_ee[j];
        g_den[b0g + tid] = s_S[tid] + __logf(s);
    }
}

// =====================================================================
// Final mean reduce
// =====================================================================
__global__ void crf_reduce_kernel(float* __restrict__ out)
{
    __shared__ float sh[BB];
    int t = threadIdx.x;
    sh[t] = g_num[t] - g_den[t];
    __syncthreads();
#pragma unroll
    for (int o = BB / 2; o > 0; o >>= 1) {
        if (t < o) sh[t] += sh[t + o];
        __syncthreads();
    }
    if (t == 0) out[0] = sh[0] * (1.0f / (float)BB);
}

extern "C" void kernel_launch(void* const* d_in, const int* in_sizes, int n_in,
                              void* d_out, int out_size)
{
    const float* em    = (const float*)d_in[0];
    const int*   tags  = (const int*)d_in[1];
    const int*   masks = (const int*)d_in[2];
    const float* start = (const float*)d_in[3];
    const float* endt  = (const float*)d_in[4];
    const float* trans = (const float*)d_in[5];
    float* out = (float*)d_out;

    crf_fused_kernel<<<BB / NB, ALL_T>>>(em, tags, masks, start, endt, trans);
    crf_reduce_kernel<<<1, BB>>>(out);
}